// round 12
// baseline (speedup 1.0000x reference)
#include <cuda_runtime.h>
#include <cuda_fp16.h>
#include <math.h>
#include <stdint.h>

#define H    256
#define BSZ  256
#define TLEN 128
#define G4   1024
#define DIN  512
#define SKA  264
#define SKB  520

__device__ float  g_wx[(size_t)2 * TLEN * 2048 * BSZ];   // [d][t][j2][b], j2<1024 gates, >=1024 xz
__device__ float  g_out0[(size_t)BSZ * TLEN * 512];
__device__ float  g_h[2 * BSZ * H];
__device__ float  g_c[2 * BSZ * H];
__device__ __half g_scanwf0[2 * 16 * 112 * 256];   // merged scan weights L0 [d][kt][mt(112)][lane][8]
__device__ __half g_scanwf1[2 * 16 * 112 * 256];
__device__ __half g_outpf[32 * 16 * 256];
__device__ __half g_xpf[32 * 4 * 256];
__device__ __half g_wihcf0[(size_t)2 * 8 * 128 * 256];    // wx weights L0 (M=2048 -> MT=128)
__device__ __half g_wihcf1[(size_t)2 * 32 * 128 * 256];
__device__ __half g_xbf[(size_t)TLEN * 32 * 4096];
__device__ float  g_tmpW[2 * 1024 * 512];

__device__ __forceinline__ float sigf(float x) { return 1.0f / (1.0f + __expf(-x)); }
__device__ __forceinline__ float tanha(float x) {
    float r; asm("tanh.approx.f32 %0, %1;" : "=f"(r) : "f"(x)); return r;
}

__device__ __forceinline__ void mma16816(float d[4], unsigned a0, unsigned a1, unsigned a2,
                                         unsigned a3, unsigned b0, unsigned b1) {
    asm volatile(
        "mma.sync.aligned.m16n8k16.row.col.f32.f16.f16.f32 "
        "{%0,%1,%2,%3},{%4,%5,%6,%7},{%8,%9},{%0,%1,%2,%3};"
        : "+f"(d[0]), "+f"(d[1]), "+f"(d[2]), "+f"(d[3])
        : "r"(a0), "r"(a1), "r"(a2), "r"(a3), "r"(b0), "r"(b1));
}

// W[j][k] (row-major, row stride K) -> A-frag-native at tile offset mt0 within MTtot tiles
__global__ void prepfrag2(const float* __restrict__ W, __half* __restrict__ out,
                          int MTtot, int mt0, int MT, int KT, int J, int K)
{
    int idx = blockIdx.x * 256 + threadIdx.x;
    if (idx >= MT * KT * 256) return;
    int h = idx & 7, lane = (idx >> 3) & 31;
    int tile = idx >> 8;
    int mt = tile % MT, kt = tile / MT;
    int reg = h >> 1;
    int j = mt * 16 + (lane >> 2) + (reg & 1) * 8;
    int k = kt * 16 + (lane & 3) * 2 + (reg >> 1) * 8 + (h & 1);
    out[(((size_t)kt * MTtot + mt0 + mt) * 32 + lane) * 8 + h] =
        (j < J) ? __float2half(W[(size_t)j * K + k]) : __float2half(0.0f);
}

// C[j][n] = sum_{m<256} A[j][m] * B[m][n]; A=in_proj (1024x256); B row stride N; z batches B,C
__global__ void comb_gemm(const float* __restrict__ A, const float* __restrict__ Bsrc,
                          float* __restrict__ C, int N, long Bz, long Cz)
{
    const float* B = Bsrc + (size_t)blockIdx.z * Bz;
    float* Cd = C + (size_t)blockIdx.z * Cz;
    int j0 = blockIdx.y * 64, n0 = blockIdx.x * 64;
    int tid = threadIdx.x;
    int tx = tid & 15, ty = tid >> 4;
    __shared__ float As[16][65], Bs[16][65];
    float acc[4][4] = {};
    for (int m0 = 0; m0 < 256; m0 += 16) {
        for (int e = tid; e < 1024; e += 256) {
            int rw = e >> 4, cl = e & 15;
            As[cl][rw] = A[(size_t)(j0 + rw) * 256 + m0 + cl];
        }
        for (int e = tid; e < 1024; e += 256) {
            int rw = e >> 6, cl = e & 63;
            Bs[rw][cl] = B[(size_t)(m0 + rw) * N + n0 + cl];
        }
        __syncthreads();
#pragma unroll
        for (int k = 0; k < 16; k++) {
            float av[4], bv[4];
#pragma unroll
            for (int i = 0; i < 4; i++) { av[i] = As[k][ty * 4 + i]; bv[i] = Bs[k][tx * 4 + i]; }
#pragma unroll
            for (int i = 0; i < 4; i++)
#pragma unroll
                for (int l = 0; l < 4; l++) acc[i][l] += av[i] * bv[l];
        }
        __syncthreads();
    }
#pragma unroll
    for (int i = 0; i < 4; i++)
#pragma unroll
        for (int l = 0; l < 4; l++)
            Cd[(size_t)(j0 + ty * 4 + i) * N + n0 + tx * 4 + l] = acc[i][l];
}

// X[b][t][K] fp32 -> B-frag fp16 stream
__global__ void conv_bfrag(const float* __restrict__ X, __half* __restrict__ out,
                           int KT, int Kfull)
{
    int widx = blockIdx.x * 256 + threadIdx.x;
    if (widx >= TLEN * KT * 2048) return;
    int which = widx & 1;
    int lane  = (widx >> 1) & 31;
    int nt    = (widx >> 6) & 31;
    int kt    = (widx >> 11) % KT;
    int t     = (widx >> 11) / KT;
    int k = kt * 16 + which * 8 + (lane & 3) * 2;
    int b = nt * 8 + (lane >> 2);
    const float* p = X + ((size_t)b * TLEN + t) * Kfull + k;
    ((__half2*)out)[widx] = __floats2half2_rn(p[0], p[1]);
}

// wx GEMM M=2048: g_wx[d][t][j2][b]
__global__ __launch_bounds__(512) void wx_hmma(const __half* __restrict__ xbf,
                                               const __half* __restrict__ wf, int KT)
{
    const int d  = blockIdx.z;
    const int jb = blockIdx.y * 128;
    const int t  = blockIdx.x;
    const int ts = d ? (TLEN - 1 - t) : t;
    const int tid = threadIdx.x;
    const int w = tid >> 5, lane = tid & 31;
    const int mt = w >> 1, nt0 = (w & 1) * 16;
    const int r = lane >> 2, c2 = (lane & 3) * 2;
    const int mtg = (jb >> 4) + mt;

    const uint4* wfa = (const uint4*)(wf + (size_t)d * KT * 128 * 256);
    const uint2* bfr = (const uint2*)xbf;

    float acc[16][4];
#pragma unroll
    for (int q = 0; q < 16; q++)
#pragma unroll
        for (int i = 0; i < 4; i++) acc[q][i] = 0.0f;

    for (int kt = 0; kt < KT; kt++) {
        uint4 af = wfa[((size_t)kt * 128 + mtg) * 32 + lane];
        const uint2* bb = bfr + ((size_t)(ts * KT + kt)) * 1024 + nt0 * 32 + lane;
#pragma unroll
        for (int q = 0; q < 16; q++) {
            uint2 bv = bb[q * 32];
            mma16816(acc[q], af.x, af.y, af.z, af.w, bv.x, bv.y);
        }
    }
    const int j = jb + mt * 16 + r;
    float* obase = g_wx + (((size_t)(d * TLEN + t)) * 2048 + j) * BSZ;
#pragma unroll
    for (int q = 0; q < 16; q++) {
        int b = (nt0 + q) * 8 + c2;
        *(float2*)(obase + b)           = make_float2(acc[q][0], acc[q][1]);
        *(float2*)(obase + 8 * BSZ + b) = make_float2(acc[q][2], acc[q][3]);
    }
}

// ---------------- scan ----------------
struct SS {
    __half hT[8 * SKA];
    __half xmT[8 * SKB];
    __half zsT[8 * SKB];
    __half yT[8 * SKB];
    __half dtw[DIN * 16];
    float  gates[3][8 * 256];
    float  cst[8 * 256];
    float  xdbl[8 * 64];
    float  bsum[G4];
    float  cw1[DIN], cb[DIN], dm[DIN], dtb[DIN];
};

__global__ __launch_bounds__(512) void scan_kernel(
    const __half* __restrict__ scanwf,
    const float*  __restrict__ bih,
    const float*  __restrict__ bhh,
    const __half* __restrict__ outpf,
    const __half* __restrict__ xpf,
    const float*  __restrict__ conv_w,
    const float*  __restrict__ conv_b,
    const float*  __restrict__ dt_w,
    const float*  __restrict__ dt_b,
    const float*  __restrict__ Dm,
    float* __restrict__ outbuf,
    int first_layer)
{
    extern __shared__ char sraw[];
    SS* S = (SS*)sraw;
    const int tid  = threadIdx.x;
    const int w    = tid >> 5, lane = tid & 31;
    const int r    = lane >> 2, c2 = (lane & 3) * 2;
    const int nb   = lane >> 2;
    const int dd   = blockIdx.x >> 5;
    const int b0g  = (blockIdx.x & 31) * 8;
    const uint4* swf = (const uint4*)(scanwf + (size_t)dd * 16 * 112 * 256);

#pragma unroll
    for (int i = 0; i < 2; i++) {
        int j = tid + i * 512;
        S->bsum[j] = bih[dd * G4 + j] + bhh[dd * G4 + j];
    }
    S->cw1[tid] = conv_w[tid * 2 + 1];
    S->cb[tid]  = conv_b[tid];
    S->dm[tid]  = Dm[tid];
    S->dtb[tid] = dt_b[tid];
#pragma unroll
    for (int i = 0; i < 16; i++) S->dtw[tid + i * 512] = __float2half(dt_w[tid + i * 512]);
#pragma unroll
    for (int i = 0; i < 4; i++) {
        int idx = tid + i * 512;
        int n = idx >> 8, j = idx & 255;
        if (first_layer) {
            S->hT[n * SKA + j] = __float2half(0.0f);
            S->cst[idx] = 0.0f;
        } else {
            S->hT[n * SKA + j] = __float2half(g_h[((size_t)dd * BSZ + b0g + n) * H + j]);
            S->cst[idx] = g_c[((size_t)dd * BSZ + b0g + n) * H + j];
        }
    }
    __syncthreads();

    for (int t = 0; t < TLEN; t++) {
        // ---- Phase 1 (merged): [gates(768) | xz(1024)] = wx-part + h @ scanW^T ----
        float da[7][4];
        {
            const float* wxt = g_wx + ((size_t)(dd * TLEN + t)) * 2048 * BSZ;
#pragma unroll
            for (int m = 0; m < 7; m++) {
                int j2 = 256 + (w * 7 + m) * 16 + r;
                const float* p = wxt + (size_t)j2 * BSZ + b0g + c2;
                float2 lo = *(const float2*)p;
                float2 hi = *(const float2*)(p + 8 * BSZ);
                da[m][0] = lo.x; da[m][1] = lo.y; da[m][2] = hi.x; da[m][3] = hi.y;
            }
        }
#pragma unroll 2
        for (int kt = 0; kt < 16; kt++) {
            unsigned bb0 = *(const unsigned*)&S->hT[nb * SKA + kt * 16 + c2];
            unsigned bb1 = *(const unsigned*)&S->hT[nb * SKA + kt * 16 + c2 + 8];
#pragma unroll
            for (int m = 0; m < 7; m++) {
                uint4 f = swf[((size_t)kt * 112 + w * 7 + m) * 32 + lane];
                mma16816(da[m], f.x, f.y, f.z, f.w, bb0, bb1);
            }
        }
#pragma unroll
        for (int m = 0; m < 7; m++) {
            int mg = w * 7 + m;
            if (mg < 48) {
                int jr = mg * 16 + r;             // 0..767
                int gi = jr >> 8, jo = jr & 255;
                S->gates[gi][(c2    ) * 256 + jo    ] = da[m][0];
                S->gates[gi][(c2 + 1) * 256 + jo    ] = da[m][1];
                S->gates[gi][(c2    ) * 256 + jo + 8] = da[m][2];
                S->gates[gi][(c2 + 1) * 256 + jo + 8] = da[m][3];
            } else if (mg < 80) {                 // xm = silu(xz*cw1+cb)
                int xzj = (mg - 48) * 16 + r;
#pragma unroll
                for (int q = 0; q < 4; q++) {
                    int jj = xzj + (q >> 1) * 8, n = c2 + (q & 1);
                    float pre = da[m][q] * S->cw1[jj] + S->cb[jj];
                    S->xmT[n * SKB + jj] = __float2half(pre * sigf(pre));
                }
            } else {                              // zs = silu(z)
                int xzj = (mg - 48) * 16 + r - 512;
#pragma unroll
                for (int q = 0; q < 4; q++) {
                    int jj = xzj + (q >> 1) * 8, n = c2 + (q & 1);
                    float z = da[m][q];
                    S->zsT[n * SKB + jj] = __float2half(z * sigf(z));
                }
            }
        }
        __syncthreads();

        // ---- C: x_dbl = xm @ x_proj^T ----
        if (w < 4) {
            float dc[4] = {0, 0, 0, 0};
#pragma unroll 4
            for (int kt = 0; kt < 32; kt++) {
                unsigned bb0 = *(const unsigned*)&S->xmT[nb * SKB + kt * 16 + c2];
                unsigned bb1 = *(const unsigned*)&S->xmT[nb * SKB + kt * 16 + c2 + 8];
                uint4 f = ((const uint4*)xpf)[(kt * 4 + w) * 32 + lane];
                mma16816(dc, f.x, f.y, f.z, f.w, bb0, bb1);
            }
            int o = w * 16 + r;
            S->xdbl[(c2    ) * 64 + o    ] = dc[0];
            S->xdbl[(c2 + 1) * 64 + o    ] = dc[1];
            S->xdbl[(c2    ) * 64 + o + 8] = dc[2];
            S->xdbl[(c2 + 1) * 64 + o + 8] = dc[3];
        }
        __syncthreads();

        // ---- D: bcs via warp shuffle, delta/softplus, y ----
        {
            int nl = lane >> 2, s0 = (lane & 3) * 4;
            float part = 0.0f;
#pragma unroll
            for (int s = 0; s < 4; s++)
                part += S->xdbl[nl * 64 + 16 + s0 + s] * S->xdbl[nl * 64 + 32 + s0 + s];
            part += __shfl_xor_sync(0xffffffffu, part, 1);
            part += __shfl_xor_sync(0xffffffffu, part, 2);
            float bcsv[8];
#pragma unroll
            for (int n = 0; n < 8; n++) bcsv[n] = __shfl_sync(0xffffffffu, part, n * 4);

            int j = tid;
            float wr[16];
#pragma unroll
            for (int q = 0; q < 16; q++) wr[q] = __half2float(S->dtw[j * 16 + q]);
            float dtbj = S->dtb[j], dmj = S->dm[j];
#pragma unroll
            for (int n = 0; n < 8; n++) {
                float s = dtbj;
#pragma unroll
                for (int rr = 0; rr < 16; rr++) s += S->xdbl[n * 64 + rr] * wr[rr];
                float delta = fmaxf(s, 0.0f) + __logf(1.0f + __expf(-fabsf(s)));
                float y = (delta * bcsv[n] + dmj) * __half2float(S->xmT[n * SKB + j])
                                                  * __half2float(S->zsT[n * SKB + j]);
                S->yT[n * SKB + j] = __float2half(y);
            }
        }
        __syncthreads();

        // ---- E: mamba_out = y @ out_proj^T ----
        float de[4] = {0, 0, 0, 0};
#pragma unroll 4
        for (int kt = 0; kt < 32; kt++) {
            unsigned bb0 = *(const unsigned*)&S->yT[nb * SKB + kt * 16 + c2];
            unsigned bb1 = *(const unsigned*)&S->yT[nb * SKB + kt * 16 + c2 + 8];
            uint4 f = ((const uint4*)outpf)[(kt * 16 + w) * 32 + lane];
            mma16816(de, f.x, f.y, f.z, f.w, bb0, bb1);
        }

        // ---- F: gates, state, output ----
        {
            int t_out = dd ? (TLEN - 1 - t) : t;
#pragma unroll
            for (int q = 0; q < 4; q++) {
                int jj = w * 16 + r + (q >> 1) * 8;
                int n  = c2 + (q & 1);
                int ix = n * 256 + jj;
                float iv = sigf(de[q] + S->bsum[jj]);
                float fv = sigf(S->gates[0][ix] + S->bsum[256 + jj]);
                float gv = tanha(S->gates[1][ix] + S->bsum[512 + jj]);
                float ov = sigf(S->gates[2][ix] + S->bsum[768 + jj]);
                float cn = fv * S->cst[ix] + iv * gv;
                float hn = ov * tanha(cn);
                S->cst[ix] = cn;
                S->hT[n * SKA + jj] = __float2half(hn);
                outbuf[((size_t)(b0g + n) * TLEN + t_out) * 512 + dd * 256 + jj] = hn;
            }
        }
        __syncthreads();
    }

#pragma unroll
    for (int i = 0; i < 4; i++) {
        int idx = tid + i * 512;
        int n = idx >> 8, j = idx & 255;
        g_h[((size_t)dd * BSZ + b0g + n) * H + j] = __half2float(S->hT[n * SKA + j]);
        g_c[((size_t)dd * BSZ + b0g + n) * H + j] = S->cst[idx];
    }
}

// =====================================================================
extern "C" void kernel_launch(void* const* d_in, const int* in_sizes, int n_in,
                              void* d_out, int out_size)
{
    (void)in_sizes; (void)n_in; (void)out_size;
    const float* x        = (const float*)d_in[0];
    const float* w_ih_l0  = (const float*)d_in[1];
    const float* w_hh_l0  = (const float*)d_in[2];
    const float* b_ih_l0  = (const float*)d_in[3];
    const float* b_hh_l0  = (const float*)d_in[4];
    const float* w_ih_l1  = (const float*)d_in[5];
    const float* w_hh_l1  = (const float*)d_in[6];
    const float* b_ih_l1  = (const float*)d_in[7];
    const float* b_hh_l1  = (const float*)d_in[8];
    const float* in_proj  = (const float*)d_in[9];
    const float* conv_w   = (const float*)d_in[10];
    const float* conv_b   = (const float*)d_in[11];
    const float* x_proj   = (const float*)d_in[12];
    const float* dt_w     = (const float*)d_in[13];
    const float* dt_b     = (const float*)d_in[14];
    const float* Dm       = (const float*)d_in[15];
    const float* out_proj = (const float*)d_in[16];
    float* out = (float*)d_out;

    static int inited = 0;
    int smem_bytes = (int)sizeof(SS);
    if (!inited) {
        cudaFuncSetAttribute(scan_kernel, cudaFuncAttributeMaxDynamicSharedMemorySize, smem_bytes);
        inited = 1;
    }

    float*  out0;   cudaGetSymbolAddress((void**)&out0,   g_out0);
    float*  tmpW;   cudaGetSymbolAddress((void**)&tmpW,   g_tmpW);
    __half* swf0;   cudaGetSymbolAddress((void**)&swf0,   g_scanwf0);
    __half* swf1;   cudaGetSymbolAddress((void**)&swf1,   g_scanwf1);
    __half* outpf;  cudaGetSymbolAddress((void**)&outpf,  g_outpf);
    __half* xpf;    cudaGetSymbolAddress((void**)&xpf,    g_xpf);
    __half* wcf0;   cudaGetSymbolAddress((void**)&wcf0,   g_wihcf0);
    __half* wcf1;   cudaGetSymbolAddress((void**)&wcf1,   g_wihcf1);
    __half* xbf;    cudaGetSymbolAddress((void**)&xbf,    g_xbf);

    // ---- shared preps ----
    prepfrag2<<<(32 * 16 * 256 + 255) / 256, 256>>>(out_proj, outpf, 16, 0, 16, 32, 256, 512);
    prepfrag2<<<(32 * 4 * 256 + 255) / 256, 256>>>(x_proj, xpf, 4, 0, 4, 32, 48, 512);

    const int NP1 = (16 * 64 * 256 + 255) / 256;   // MT=64 frag prep blocks
    const int NP48 = (16 * 48 * 256 + 255) / 256;

    // scan weights (both layers): M2 = inP @ Whh_u, gates = Whh rows 256..1023
    comb_gemm<<<dim3(4, 16, 2), 256>>>(in_proj, w_hh_l0, tmpW, 256, (long)G4 * 256, (long)G4 * 256);
    for (int d = 0; d < 2; d++) {
        prepfrag2<<<NP1, 256>>>(tmpW + (size_t)d * G4 * 256, swf0 + (size_t)d * 16 * 112 * 256,
                                112, 48, 64, 16, 1024, 256);
        prepfrag2<<<NP48, 256>>>(w_hh_l0 + (size_t)d * G4 * 256 + 256 * 256,
                                 swf0 + (size_t)d * 16 * 112 * 256, 112, 0, 48, 16, 768, 256);
    }
    comb_gemm<<<dim3(4, 16, 2), 256>>>(in_proj, w_hh_l1, tmpW, 256, (long)G4 * 256, (long)G4 * 256);
    for (int d = 0; d < 2; d++) {
        prepfrag2<<<NP1, 256>>>(tmpW + (size_t)d * G4 * 256, swf1 + (size_t)d * 16 * 112 * 256,
                                112, 48, 64, 16, 1024, 256);
        prepfrag2<<<NP48, 256>>>(w_hh_l1 + (size_t)d * G4 * 256 + 256 * 256,
                                 swf1 + (size_t)d * 16 * 112 * 256, 112, 0, 48, 16, 768, 256);
    }

    // wx weights L0: [w_ih | inP @ w_ih_u], K=128
    comb_gemm<<<dim3(2, 16, 2), 256>>>(in_proj, w_ih_l0, tmpW, 128, (long)G4 * 128, (long)G4 * 128);
    for (int d = 0; d < 2; d++) {
        prepfrag2<<<(8 * 64 * 256 + 255) / 256, 256>>>(w_ih_l0 + (size_t)d * G4 * 128,
            wcf0 + (size_t)d * 8 * 128 * 256, 128, 0, 64, 8, 1024, 128);
        prepfrag2<<<(8 * 64 * 256 + 255) / 256, 256>>>(tmpW + (size_t)d * G4 * 128,
            wcf0 + (size_t)d * 8 * 128 * 256, 128, 64, 64, 8, 1024, 128);
    }
    // wx weights L1: K=512
    comb_gemm<<<dim3(8, 16, 2), 256>>>(in_proj, w_ih_l1, tmpW, 512, (long)G4 * 512, (long)G4 * 512);
    for (int d = 0; d < 2; d++) {
        prepfrag2<<<(32 * 64 * 256 + 255) / 256, 256>>>(w_ih_l1 + (size_t)d * G4 * 512,
            wcf1 + (size_t)d * 32 * 128 * 256, 128, 0, 64, 32, 1024, 512);
        prepfrag2<<<(32 * 64 * 256 + 255) / 256, 256>>>(tmpW + (size_t)d * G4 * 512,
            wcf1 + (size_t)d * 32 * 128 * 256, 128, 64, 64, 32, 1024, 512);
    }

    // ---- layer 0 ----
    conv_bfrag<<<(TLEN * 8 * 2048 + 255) / 256, 256>>>(x, xbf, 8, 128);
    wx_hmma<<<dim3(TLEN, 16, 2), 512>>>(xbf, wcf0, 8);
    scan_kernel<<<64, 512, smem_bytes>>>(swf0, b_ih_l0, b_hh_l0, outpf, xpf,
        conv_w, conv_b, dt_w, dt_b, Dm, out0, 1);

    // ---- layer 1 ----
    conv_bfrag<<<(TLEN * 32 * 2048 + 255) / 256, 256>>>(out0, xbf, 32, 512);
    wx_hmma<<<dim3(TLEN, 16, 2), 512>>>(xbf, wcf1, 32);
    scan_kernel<<<64, 512, smem_bytes>>>(swf1, b_ih_l1, b_hh_l1, outpf, xpf,
        conv_w, conv_b, dt_w, dt_b, Dm, out, 0);
}

// round 14
// speedup vs baseline: 1.2650x; 1.2650x over previous
#include <cuda_runtime.h>
#include <cuda_fp16.h>
#include <math.h>
#include <stdint.h>

#define H    256
#define BSZ  256
#define TLEN 128
#define G4   1024
#define DIN  512
#define SKA  264
#define SKB  520

__device__ float  g_wx[(size_t)2 * TLEN * G4 * BSZ];   // [d][t][j][b]
__device__ float  g_out0[(size_t)BSZ * TLEN * 512];
__device__ float  g_h[2 * BSZ * H];
__device__ float  g_c[2 * BSZ * H];
__device__ __half g_whhf[2 * 16 * 64 * 256];
__device__ __half g_inpf[16 * 64 * 256];
__device__ __half g_outpf[32 * 16 * 256];
__device__ __half g_xpf[32 * 4 * 256];
__device__ __half g_wihf0[2 * 8 * 64 * 256];
__device__ __half g_wihf1[2 * 32 * 64 * 256];
__device__ __half g_xbf[(size_t)TLEN * 32 * 4096];

__device__ __forceinline__ float sigf(float x) { return 1.0f / (1.0f + __expf(-x)); }
__device__ __forceinline__ float tanha(float x) {
    float r; asm("tanh.approx.f32 %0, %1;" : "=f"(r) : "f"(x)); return r;
}

__device__ __forceinline__ void mma16816(float d[4], unsigned a0, unsigned a1, unsigned a2,
                                         unsigned a3, unsigned b0, unsigned b1) {
    asm volatile(
        "mma.sync.aligned.m16n8k16.row.col.f32.f16.f16.f32 "
        "{%0,%1,%2,%3},{%4,%5,%6,%7},{%8,%9},{%0,%1,%2,%3};"
        : "+f"(d[0]), "+f"(d[1]), "+f"(d[2]), "+f"(d[3])
        : "r"(a0), "r"(a1), "r"(a2), "r"(a3), "r"(b0), "r"(b1));
}

// W[j][k] row-major -> A-frag-native: out[((kt*MT+mt)*32+lane)*8 + h]
__global__ void prepfrag(const float* __restrict__ W, __half* __restrict__ out,
                         int MT, int KT, int J)
{
    int idx = blockIdx.x * 256 + threadIdx.x;
    if (idx >= MT * KT * 256) return;
    int h = idx & 7, lane = (idx >> 3) & 31;
    int tile = idx >> 8;
    int mt = tile % MT, kt = tile / MT;
    int reg = h >> 1;
    int j = mt * 16 + (lane >> 2) + (reg & 1) * 8;
    int k = kt * 16 + (lane & 3) * 2 + (reg >> 1) * 8 + (h & 1);
    out[idx] = (j < J) ? __float2half(W[(size_t)j * (KT * 16) + k]) : __float2half(0.0f);
}

// X[b][t][K] fp32 -> B-frag fp16 stream
__global__ void conv_bfrag(const float* __restrict__ X, __half* __restrict__ out,
                           int KT, int Kfull)
{
    int widx = blockIdx.x * 256 + threadIdx.x;
    if (widx >= TLEN * KT * 2048) return;
    int which = widx & 1;
    int lane  = (widx >> 1) & 31;
    int nt    = (widx >> 6) & 31;
    int kt    = (widx >> 11) % KT;
    int t     = (widx >> 11) / KT;
    int k = kt * 16 + which * 8 + (lane & 3) * 2;
    int b = nt * 8 + (lane >> 2);
    const float* p = X + ((size_t)b * TLEN + t) * Kfull + k;
    ((__half2*)out)[widx] = __floats2half2_rn(p[0], p[1]);
}

// ---------------- HMMA wx GEMM: g_wx[d][t][j][b] ----------------
__global__ __launch_bounds__(512) void wx_hmma(const __half* __restrict__ xbf,
                                               const __half* __restrict__ wf, int KT)
{
    const int d  = blockIdx.z;
    const int jb = blockIdx.y * 128;
    const int t  = blockIdx.x;
    const int ts = d ? (TLEN - 1 - t) : t;
    const int tid = threadIdx.x;
    const int w = tid >> 5, lane = tid & 31;
    const int mt = w >> 1, nt0 = (w & 1) * 16;
    const int r = lane >> 2, c2 = (lane & 3) * 2;
    const int mtg = (jb >> 4) + mt;

    const uint4* wfa = (const uint4*)(wf + (size_t)d * KT * 64 * 256);
    const uint2* bfr = (const uint2*)xbf;

    float acc[16][4];
#pragma unroll
    for (int q = 0; q < 16; q++)
#pragma unroll
        for (int i = 0; i < 4; i++) acc[q][i] = 0.0f;

    for (int kt = 0; kt < KT; kt++) {
        uint4 af = wfa[((size_t)kt * 64 + mtg) * 32 + lane];
        const uint2* bb = bfr + ((size_t)(ts * KT + kt)) * 1024 + nt0 * 32 + lane;
#pragma unroll
        for (int q = 0; q < 16; q++) {
            uint2 bv = bb[q * 32];
            mma16816(acc[q], af.x, af.y, af.z, af.w, bv.x, bv.y);
        }
    }
    const int j = jb + mt * 16 + r;
    float* obase = g_wx + (((size_t)(d * TLEN + t)) * G4 + j) * BSZ;
#pragma unroll
    for (int q = 0; q < 16; q++) {
        int b = (nt0 + q) * 8 + c2;
        *(float2*)(obase + b)           = make_float2(acc[q][0], acc[q][1]);
        *(float2*)(obase + 8 * BSZ + b) = make_float2(acc[q][2], acc[q][3]);
    }
}

// ---------------- scan: 1024 threads ----------------
struct SS {
    __half hT[8 * SKA];
    __half uT[8 * SKA];
    __half xmT[8 * SKB];
    __half zsT[8 * SKB];
    __half yT[8 * SKB];
    __half dtw[DIN * 16];
    float  gates[3][8 * 256];
    float  cst[8 * 256];
    float  xdbl[8 * 64];
    float  bsum[G4];
    float  cw1[DIN], cb[DIN], dm[DIN], dtb[DIN];
};

__global__ __launch_bounds__(1024) void scan_kernel(
    const __half* __restrict__ whhf,
    const float*  __restrict__ bih,
    const float*  __restrict__ bhh,
    const __half* __restrict__ inpf,
    const __half* __restrict__ outpf,
    const __half* __restrict__ xpf,
    const float*  __restrict__ conv_w,
    const float*  __restrict__ conv_b,
    const float*  __restrict__ dt_w,
    const float*  __restrict__ dt_b,
    const float*  __restrict__ Dm,
    float* __restrict__ outbuf,
    int first_layer)
{
    extern __shared__ char sraw[];
    SS* S = (SS*)sraw;
    const int tid  = threadIdx.x;
    const int w    = tid >> 5, lane = tid & 31;
    const int r    = lane >> 2, c2 = (lane & 3) * 2;
    const int nb   = lane >> 2;
    const int dd   = blockIdx.x >> 5;
    const int b0g  = (blockIdx.x & 31) * 8;
    const uint4* whw = (const uint4*)(whhf + (size_t)dd * 16 * 64 * 256);

    // ---- init ----
    S->bsum[tid] = bih[dd * G4 + tid] + bhh[dd * G4 + tid];
    if (tid < 512) {
        S->cw1[tid] = conv_w[tid * 2 + 1];
        S->cb[tid]  = conv_b[tid];
        S->dm[tid]  = Dm[tid];
        S->dtb[tid] = dt_b[tid];
    }
#pragma unroll
    for (int i = 0; i < 8; i++) S->dtw[tid + i * 1024] = __float2half(dt_w[tid + i * 1024]);
#pragma unroll
    for (int i = 0; i < 2; i++) {
        int idx = tid + i * 1024;
        int n = idx >> 8, j = idx & 255;
        if (first_layer) {
            S->hT[n * SKA + j] = __float2half(0.0f);
            S->cst[idx] = 0.0f;
        } else {
            S->hT[n * SKA + j] = __float2half(g_h[((size_t)dd * BSZ + b0g + n) * H + j]);
            S->cst[idx] = g_c[((size_t)dd * BSZ + b0g + n) * H + j];
        }
    }
    __syncthreads();

    for (int t = 0; t < TLEN; t++) {
        // ---- A: g = wx + h @ Whh^T  (32 warps x 2 m-tiles) ----
        float da[2][4];
        {
            const float* wxt = g_wx + ((size_t)(dd * TLEN + t)) * G4 * BSZ;
#pragma unroll
            for (int m = 0; m < 2; m++) {
                int j = (w * 2 + m) * 16 + r;
                const float* p = wxt + (size_t)j * BSZ + b0g + c2;
                float2 lo = *(const float2*)p;
                float2 hi = *(const float2*)(p + 8 * BSZ);
                da[m][0] = lo.x; da[m][1] = lo.y; da[m][2] = hi.x; da[m][3] = hi.y;
            }
        }
#pragma unroll 4
        for (int kt = 0; kt < 16; kt++) {
            unsigned bb0 = *(const unsigned*)&S->hT[nb * SKA + kt * 16 + c2];
            unsigned bb1 = *(const unsigned*)&S->hT[nb * SKA + kt * 16 + c2 + 8];
#pragma unroll
            for (int m = 0; m < 2; m++) {
                uint4 f = whw[(kt * 64 + w * 2 + m) * 32 + lane];
                mma16816(da[m], f.x, f.y, f.z, f.w, bb0, bb1);
            }
        }
#pragma unroll
        for (int m = 0; m < 2; m++) {
            int j = (w * 2 + m) * 16 + r;
            if (j < 256) {
                S->uT[(c2    ) * SKA + j    ] = __float2half(da[m][0]);
                S->uT[(c2 + 1) * SKA + j    ] = __float2half(da[m][1]);
                S->uT[(c2    ) * SKA + j + 8] = __float2half(da[m][2]);
                S->uT[(c2 + 1) * SKA + j + 8] = __float2half(da[m][3]);
            } else {
                int gi = (j >> 8) - 1, jo = j & 255;
                S->gates[gi][(c2    ) * 256 + jo    ] = da[m][0];
                S->gates[gi][(c2 + 1) * 256 + jo    ] = da[m][1];
                S->gates[gi][(c2    ) * 256 + jo + 8] = da[m][2];
                S->gates[gi][(c2 + 1) * 256 + jo + 8] = da[m][3];
            }
        }
        __syncthreads();

        // ---- B: xz = u @ in_proj^T ----
#pragma unroll
        for (int m = 0; m < 2; m++)
#pragma unroll
            for (int q = 0; q < 4; q++) da[m][q] = 0.0f;
#pragma unroll 4
        for (int kt = 0; kt < 16; kt++) {
            unsigned bb0 = *(const unsigned*)&S->uT[nb * SKA + kt * 16 + c2];
            unsigned bb1 = *(const unsigned*)&S->uT[nb * SKA + kt * 16 + c2 + 8];
#pragma unroll
            for (int m = 0; m < 2; m++) {
                uint4 f = ((const uint4*)inpf)[(kt * 64 + w * 2 + m) * 32 + lane];
                mma16816(da[m], f.x, f.y, f.z, f.w, bb0, bb1);
            }
        }
#pragma unroll
        for (int m = 0; m < 2; m++) {
            int j = (w * 2 + m) * 16 + r;
            if (j < 512) {
#pragma unroll
                for (int q = 0; q < 4; q++) {
                    int jj = j + (q >> 1) * 8, n = c2 + (q & 1);
                    float pre = da[m][q] * S->cw1[jj] + S->cb[jj];
                    S->xmT[n * SKB + jj] = __float2half(pre * sigf(pre));
                }
            } else {
                int jz = j - 512;
#pragma unroll
                for (int q = 0; q < 4; q++) {
                    int jj = jz + (q >> 1) * 8, n = c2 + (q & 1);
                    float z = da[m][q];
                    S->zsT[n * SKB + jj] = __float2half(z * sigf(z));
                }
            }
        }
        __syncthreads();

        // ---- C: x_dbl = xm @ x_proj^T (warps 0-3) ----
        if (w < 4) {
            float dc[4] = {0, 0, 0, 0};
#pragma unroll 4
            for (int kt = 0; kt < 32; kt++) {
                unsigned bb0 = *(const unsigned*)&S->xmT[nb * SKB + kt * 16 + c2];
                unsigned bb1 = *(const unsigned*)&S->xmT[nb * SKB + kt * 16 + c2 + 8];
                uint4 f = ((const uint4*)xpf)[(kt * 4 + w) * 32 + lane];
                mma16816(dc, f.x, f.y, f.z, f.w, bb0, bb1);
            }
            int o = w * 16 + r;
            S->xdbl[(c2    ) * 64 + o    ] = dc[0];
            S->xdbl[(c2 + 1) * 64 + o    ] = dc[1];
            S->xdbl[(c2    ) * 64 + o + 8] = dc[2];
            S->xdbl[(c2 + 1) * 64 + o + 8] = dc[3];
        }
        __syncthreads();

        // ---- D: bcs inline, delta/softplus, y  (1024 thr: j = tid&511, 4 n each) ----
        {
            int j = tid & 511, nh = tid >> 9;
            float wr[16];
#pragma unroll
            for (int q = 0; q < 16; q++) wr[q] = __half2float(S->dtw[j * 16 + q]);
            float dtbj = S->dtb[j], dmj = S->dm[j];
#pragma unroll
            for (int nn = 0; nn < 4; nn++) {
                int n = nh * 4 + nn;
                float bcs = 0.0f;
#pragma unroll
                for (int ss = 0; ss < 16; ss++)
                    bcs += S->xdbl[n * 64 + 16 + ss] * S->xdbl[n * 64 + 32 + ss];
                float s = dtbj;
#pragma unroll
                for (int rr = 0; rr < 16; rr++) s += S->xdbl[n * 64 + rr] * wr[rr];
                float delta = fmaxf(s, 0.0f) + __logf(1.0f + __expf(-fabsf(s)));
                float y = (delta * bcs + dmj) * __half2float(S->xmT[n * SKB + j])
                                              * __half2float(S->zsT[n * SKB + j]);
                S->yT[n * SKB + j] = __float2half(y);
            }
        }
        __syncthreads();

        // ---- E+F: warps 0-15 ----
        if (w < 16) {
            float de[4] = {0, 0, 0, 0};
#pragma unroll 4
            for (int kt = 0; kt < 32; kt++) {
                unsigned bb0 = *(const unsigned*)&S->yT[nb * SKB + kt * 16 + c2];
                unsigned bb1 = *(const unsigned*)&S->yT[nb * SKB + kt * 16 + c2 + 8];
                uint4 f = ((const uint4*)outpf)[(kt * 16 + w) * 32 + lane];
                mma16816(de, f.x, f.y, f.z, f.w, bb0, bb1);
            }
            int t_out = dd ? (TLEN - 1 - t) : t;
#pragma unroll
            for (int q = 0; q < 4; q++) {
                int jj = w * 16 + r + (q >> 1) * 8;
                int n  = c2 + (q & 1);
                int ix = n * 256 + jj;
                float iv = sigf(de[q] + S->bsum[jj]);
                float fv = sigf(S->gates[0][ix] + S->bsum[256 + jj]);
                float gv = tanha(S->gates[1][ix] + S->bsum[512 + jj]);
                float ov = sigf(S->gates[2][ix] + S->bsum[768 + jj]);
                float cn = fv * S->cst[ix] + iv * gv;
                float hn = ov * tanha(cn);
                S->cst[ix] = cn;
                S->hT[n * SKA + jj] = __float2half(hn);
                outbuf[((size_t)(b0g + n) * TLEN + t_out) * 512 + dd * 256 + jj] = hn;
            }
        }
        __syncthreads();
    }

#pragma unroll
    for (int i = 0; i < 2; i++) {
        int idx = tid + i * 1024;
        int n = idx >> 8, j = idx & 255;
        g_h[((size_t)dd * BSZ + b0g + n) * H + j] = __half2float(S->hT[n * SKA + j]);
        g_c[((size_t)dd * BSZ + b0g + n) * H + j] = S->cst[idx];
    }
}

// =====================================================================
extern "C" void kernel_launch(void* const* d_in, const int* in_sizes, int n_in,
                              void* d_out, int out_size)
{
    (void)in_sizes; (void)n_in; (void)out_size;
    const float* x        = (const float*)d_in[0];
    const float* w_ih_l0  = (const float*)d_in[1];
    const float* w_hh_l0  = (const float*)d_in[2];
    const float* b_ih_l0  = (const float*)d_in[3];
    const float* b_hh_l0  = (const float*)d_in[4];
    const float* w_ih_l1  = (const float*)d_in[5];
    const float* w_hh_l1  = (const float*)d_in[6];
    const float* b_ih_l1  = (const float*)d_in[7];
    const float* b_hh_l1  = (const float*)d_in[8];
    const float* in_proj  = (const float*)d_in[9];
    const float* conv_w   = (const float*)d_in[10];
    const float* conv_b   = (const float*)d_in[11];
    const float* x_proj   = (const float*)d_in[12];
    const float* dt_w     = (const float*)d_in[13];
    const float* dt_b     = (const float*)d_in[14];
    const float* Dm       = (const float*)d_in[15];
    const float* out_proj = (const float*)d_in[16];
    float* out = (float*)d_out;

    static int inited = 0;
    int smem_bytes = (int)sizeof(SS);
    if (!inited) {
        cudaFuncSetAttribute(scan_kernel, cudaFuncAttributeMaxDynamicSharedMemorySize, smem_bytes);
        inited = 1;
    }

    float*  out0;   cudaGetSymbolAddress((void**)&out0,   g_out0);
    __half* whhf;   cudaGetSymbolAddress((void**)&whhf,   g_whhf);
    __half* inpf;   cudaGetSymbolAddress((void**)&inpf,   g_inpf);
    __half* outpf;  cudaGetSymbolAddress((void**)&outpf,  g_outpf);
    __half* xpf;    cudaGetSymbolAddress((void**)&xpf,    g_xpf);
    __half* wihf0;  cudaGetSymbolAddress((void**)&wihf0,  g_wihf0);
    __half* wihf1;  cudaGetSymbolAddress((void**)&wihf1,  g_wihf1);
    __half* xbf;    cudaGetSymbolAddress((void**)&xbf,    g_xbf);

    // layer-independent frag weights
    prepfrag<<<(16 * 64 * 256 + 255) / 256, 256>>>(in_proj, inpf, 64, 16, 1024);
    prepfrag<<<(32 * 16 * 256 + 255) / 256, 256>>>(out_proj, outpf, 16, 32, 256);
    prepfrag<<<(32 * 4 * 256 + 255) / 256, 256>>>(x_proj, xpf, 4, 32, 48);
    // w_ih frags (both layers, both dirs)
    prepfrag<<<(8 * 64 * 256 + 255) / 256, 256>>>(w_ih_l0, wihf0, 64, 8, 1024);
    prepfrag<<<(8 * 64 * 256 + 255) / 256, 256>>>(w_ih_l0 + (size_t)G4 * 128,
                                                  wihf0 + 8 * 64 * 256, 64, 8, 1024);
    prepfrag<<<(32 * 64 * 256 + 255) / 256, 256>>>(w_ih_l1, wihf1, 64, 32, 1024);
    prepfrag<<<(32 * 64 * 256 + 255) / 256, 256>>>(w_ih_l1 + (size_t)G4 * 512,
                                                   wihf1 + 32 * 64 * 256, 64, 32, 1024);

    // ---- layer 0 ----
    prepfrag<<<(16 * 64 * 256 + 255) / 256, 256>>>(w_hh_l0, whhf, 64, 16, 1024);
    prepfrag<<<(16 * 64 * 256 + 255) / 256, 256>>>(w_hh_l0 + (size_t)G4 * H,
                                                   whhf + 16 * 64 * 256, 64, 16, 1024);
    conv_bfrag<<<(TLEN * 8 * 2048 + 255) / 256, 256>>>(x, xbf, 8, 128);
    wx_hmma<<<dim3(TLEN, 8, 2), 512>>>(xbf, wihf0, 8);
    scan_kernel<<<64, 1024, smem_bytes>>>(whhf, b_ih_l0, b_hh_l0, inpf, outpf, xpf,
        conv_w, conv_b, dt_w, dt_b, Dm, out0, 1);

    // ---- layer 1 ----
    prepfrag<<<(16 * 64 * 256 + 255) / 256, 256>>>(w_hh_l1, whhf, 64, 16, 1024);
    prepfrag<<<(16 * 64 * 256 + 255) / 256, 256>>>(w_hh_l1 + (size_t)G4 * H,
                                                   whhf + 16 * 64 * 256, 64, 16, 1024);
    conv_bfrag<<<(TLEN * 32 * 2048 + 255) / 256, 256>>>(out0, xbf, 32, 512);
    wx_hmma<<<dim3(TLEN, 8, 2), 512>>>(xbf, wihf1, 32);
    scan_kernel<<<64, 1024, smem_bytes>>>(whhf, b_ih_l1, b_hh_l1, inpf, outpf, xpf,
        conv_w, conv_b, dt_w, dt_b, Dm, out, 0);
}

// round 15
// speedup vs baseline: 1.3944x; 1.1023x over previous
#include <cuda_runtime.h>
#include <cuda_fp16.h>
#include <math.h>
#include <stdint.h>

#define H    256
#define BSZ  256
#define TLEN 128
#define G4   1024
#define DIN  512
#define SKA  264
#define SKB  520

__device__ float  g_wx[(size_t)2 * TLEN * G4 * BSZ];   // [d][t][j][b]
__device__ float  g_out0[(size_t)BSZ * TLEN * 512];
__device__ float  g_h[2 * BSZ * H];
__device__ float  g_c[2 * BSZ * H];
__device__ __half g_whhf[2 * 16 * 64 * 256];
__device__ __half g_inpf[16 * 64 * 256];
__device__ __half g_outpf[32 * 16 * 256];
__device__ __half g_xpf[32 * 4 * 256];
__device__ __half g_wihf0[2 * 8 * 64 * 256];
__device__ __half g_wihf1[2 * 32 * 64 * 256];
__device__ __half g_xbf[(size_t)TLEN * 32 * 4096];

__device__ __forceinline__ float sigf(float x) { return 1.0f / (1.0f + __expf(-x)); }
__device__ __forceinline__ float tanha(float x) {
    float r; asm("tanh.approx.f32 %0, %1;" : "=f"(r) : "f"(x)); return r;
}

__device__ __forceinline__ void mma16816(float d[4], unsigned a0, unsigned a1, unsigned a2,
                                         unsigned a3, unsigned b0, unsigned b1) {
    asm volatile(
        "mma.sync.aligned.m16n8k16.row.col.f32.f16.f16.f32 "
        "{%0,%1,%2,%3},{%4,%5,%6,%7},{%8,%9},{%0,%1,%2,%3};"
        : "+f"(d[0]), "+f"(d[1]), "+f"(d[2]), "+f"(d[3])
        : "r"(a0), "r"(a1), "r"(a2), "r"(a3), "r"(b0), "r"(b1));
}

__device__ __forceinline__ uint32_t mapa_u32(uint32_t addr, uint32_t trank) {
    uint32_t r;
    asm("mapa.shared::cluster.u32 %0, %1, %2;" : "=r"(r) : "r"(addr), "r"(trank));
    return r;
}
__device__ __forceinline__ void stc_u16(uint32_t addr, __half v) {
    unsigned short u = *(unsigned short*)&v;
    asm volatile("st.shared::cluster.u16 [%0], %1;" :: "r"(addr), "h"(u) : "memory");
}
__device__ __forceinline__ uint32_t sh32(const void* p) {
    return (uint32_t)__cvta_generic_to_shared(p);
}
#define CLUSTER_SYNC() do { \
    asm volatile("barrier.cluster.arrive.aligned;" ::: "memory"); \
    asm volatile("barrier.cluster.wait.aligned;" ::: "memory"); \
} while (0)

// W[j][k] row-major -> A-frag-native: out[((kt*MT+mt)*32+lane)*8 + h]
__global__ void prepfrag(const float* __restrict__ W, __half* __restrict__ out,
                         int MT, int KT, int J)
{
    int idx = blockIdx.x * 256 + threadIdx.x;
    if (idx >= MT * KT * 256) return;
    int h = idx & 7, lane = (idx >> 3) & 31;
    int tile = idx >> 8;
    int mt = tile % MT, kt = tile / MT;
    int reg = h >> 1;
    int j = mt * 16 + (lane >> 2) + (reg & 1) * 8;
    int k = kt * 16 + (lane & 3) * 2 + (reg >> 1) * 8 + (h & 1);
    out[idx] = (j < J) ? __float2half(W[(size_t)j * (KT * 16) + k]) : __float2half(0.0f);
}

// X[b][t][K] fp32 -> B-frag fp16 stream
__global__ void conv_bfrag(const float* __restrict__ X, __half* __restrict__ out,
                           int KT, int Kfull)
{
    int widx = blockIdx.x * 256 + threadIdx.x;
    if (widx >= TLEN * KT * 2048) return;
    int which = widx & 1;
    int lane  = (widx >> 1) & 31;
    int nt    = (widx >> 6) & 31;
    int kt    = (widx >> 11) % KT;
    int t     = (widx >> 11) / KT;
    int k = kt * 16 + which * 8 + (lane & 3) * 2;
    int b = nt * 8 + (lane >> 2);
    const float* p = X + ((size_t)b * TLEN + t) * Kfull + k;
    ((__half2*)out)[widx] = __floats2half2_rn(p[0], p[1]);
}

// ---------------- HMMA wx GEMM: g_wx[d][t][j][b] ----------------
__global__ __launch_bounds__(512) void wx_hmma(const __half* __restrict__ xbf,
                                               const __half* __restrict__ wf, int KT)
{
    const int d  = blockIdx.z;
    const int jb = blockIdx.y * 128;
    const int t  = blockIdx.x;
    const int ts = d ? (TLEN - 1 - t) : t;
    const int tid = threadIdx.x;
    const int w = tid >> 5, lane = tid & 31;
    const int mt = w >> 1, nt0 = (w & 1) * 16;
    const int r = lane >> 2, c2 = (lane & 3) * 2;
    const int mtg = (jb >> 4) + mt;

    const uint4* wfa = (const uint4*)(wf + (size_t)d * KT * 64 * 256);
    const uint2* bfr = (const uint2*)xbf;

    float acc[16][4];
#pragma unroll
    for (int q = 0; q < 16; q++)
#pragma unroll
        for (int i = 0; i < 4; i++) acc[q][i] = 0.0f;

    for (int kt = 0; kt < KT; kt++) {
        uint4 af = wfa[((size_t)kt * 64 + mtg) * 32 + lane];
        const uint2* bb = bfr + ((size_t)(ts * KT + kt)) * 1024 + nt0 * 32 + lane;
#pragma unroll
        for (int q = 0; q < 16; q++) {
            uint2 bv = bb[q * 32];
            mma16816(acc[q], af.x, af.y, af.z, af.w, bv.x, bv.y);
        }
    }
    const int j = jb + mt * 16 + r;
    float* obase = g_wx + (((size_t)(d * TLEN + t)) * G4 + j) * BSZ;
#pragma unroll
    for (int q = 0; q < 16; q++) {
        int b = (nt0 + q) * 8 + c2;
        *(float2*)(obase + b)           = make_float2(acc[q][0], acc[q][1]);
        *(float2*)(obase + 8 * BSZ + b) = make_float2(acc[q][2], acc[q][3]);
    }
}

// ---------------- scan: 2-CTA cluster, M-split ----------------
struct SS {
    __half hT[8 * SKA];
    __half uT[8 * SKA];
    __half xmT[8 * SKB];
    __half zsT[8 * SKB];
    __half yT[8 * SKB];
    __half dtw[DIN * 16];
    float  gates[3][8 * 256];
    float  cst[8 * 256];
    float  xdbl[8 * 64];
    float  epart[2][8][32][4];
    float  bsum[G4];
    float  cw1[DIN], cb[DIN], dm[DIN], dtb[DIN];
};

__global__ __launch_bounds__(1024) __cluster_dims__(2, 1, 1)
void scan_kernel(
    const __half* __restrict__ whhf,
    const float*  __restrict__ bih,
    const float*  __restrict__ bhh,
    const __half* __restrict__ inpf,
    const __half* __restrict__ outpf,
    const __half* __restrict__ xpf,
    const float*  __restrict__ conv_w,
    const float*  __restrict__ conv_b,
    const float*  __restrict__ dt_w,
    const float*  __restrict__ dt_b,
    const float*  __restrict__ Dm,
    float* __restrict__ outbuf,
    int first_layer)
{
    extern __shared__ char sraw[];
    SS* S = (SS*)sraw;
    const int tid  = threadIdx.x;
    const int w    = tid >> 5, lane = tid & 31;
    const int r    = lane >> 2, c2 = (lane & 3) * 2;
    const int nb   = lane >> 2;
    const int p    = blockIdx.x & 1;            // cluster rank
    const int pairid = blockIdx.x >> 1;
    const int dd   = pairid >> 5;
    const int b0g  = (pairid & 31) * 8;
    const uint4* whw = (const uint4*)(whhf + (size_t)dd * 16 * 64 * 256);

    const uint32_t lbase = sh32(S);
    const uint32_t dpeer = mapa_u32(lbase, (uint32_t)(p ^ 1)) - lbase;

    // ---- init (both ranks: full copies) ----
    S->bsum[tid] = bih[dd * G4 + tid] + bhh[dd * G4 + tid];
    if (tid < 512) {
        S->cw1[tid] = conv_w[tid * 2 + 1];
        S->cb[tid]  = conv_b[tid];
        S->dm[tid]  = Dm[tid];
        S->dtb[tid] = dt_b[tid];
    }
#pragma unroll
    for (int i = 0; i < 8; i++) S->dtw[tid + i * 1024] = __float2half(dt_w[tid + i * 1024]);
#pragma unroll
    for (int i = 0; i < 2; i++) {
        int idx = tid + i * 1024;
        int n = idx >> 8, j = idx & 255;
        if (first_layer) {
            S->hT[n * SKA + j] = __float2half(0.0f);
            S->cst[idx] = 0.0f;
        } else {
            S->hT[n * SKA + j] = __float2half(g_h[((size_t)dd * BSZ + b0g + n) * H + j]);
            S->cst[idx] = g_c[((size_t)dd * BSZ + b0g + n) * H + j];
        }
    }
    __syncthreads();
    CLUSTER_SYNC();

    const int mtg = (w >> 3) * 16 + p * 8 + (w & 7);   // A/B tile for this warp
    const int sA  = w >> 3;

    for (int t = 0; t < TLEN; t++) {
        // ---- A: g = wx + h @ Whh^T  (rank's 32 tiles, 1/warp) ----
        float da[4];
        {
            const float* wxt = g_wx + ((size_t)(dd * TLEN + t)) * G4 * BSZ;
            int j = mtg * 16 + r;
            const float* pp = wxt + (size_t)j * BSZ + b0g + c2;
            float2 lo = *(const float2*)pp;
            float2 hi = *(const float2*)(pp + 8 * BSZ);
            da[0] = lo.x; da[1] = lo.y; da[2] = hi.x; da[3] = hi.y;
        }
#pragma unroll 4
        for (int kt = 0; kt < 16; kt++) {
            unsigned bb0 = *(const unsigned*)&S->hT[nb * SKA + kt * 16 + c2];
            unsigned bb1 = *(const unsigned*)&S->hT[nb * SKA + kt * 16 + c2 + 8];
            uint4 f = whw[(kt * 64 + mtg) * 32 + lane];
            mma16816(da, f.x, f.y, f.z, f.w, bb0, bb1);
        }
        {
            int j = mtg * 16 + r;
            if (sA == 0) {
                __half v0 = __float2half(da[0]), v1 = __float2half(da[1]);
                __half v2 = __float2half(da[2]), v3 = __float2half(da[3]);
                S->uT[(c2    ) * SKA + j    ] = v0;
                S->uT[(c2 + 1) * SKA + j    ] = v1;
                S->uT[(c2    ) * SKA + j + 8] = v2;
                S->uT[(c2 + 1) * SKA + j + 8] = v3;
                stc_u16(sh32(&S->uT[(c2    ) * SKA + j    ]) + dpeer, v0);
                stc_u16(sh32(&S->uT[(c2 + 1) * SKA + j    ]) + dpeer, v1);
                stc_u16(sh32(&S->uT[(c2    ) * SKA + j + 8]) + dpeer, v2);
                stc_u16(sh32(&S->uT[(c2 + 1) * SKA + j + 8]) + dpeer, v3);
            } else {
                int gi = sA - 1, jo = j & 255;
                S->gates[gi][(c2    ) * 256 + jo    ] = da[0];
                S->gates[gi][(c2 + 1) * 256 + jo    ] = da[1];
                S->gates[gi][(c2    ) * 256 + jo + 8] = da[2];
                S->gates[gi][(c2 + 1) * 256 + jo + 8] = da[3];
            }
        }
        CLUSTER_SYNC();

        // ---- B: xz = u @ in_proj^T (rank's 32 tiles) ----
#pragma unroll
        for (int q = 0; q < 4; q++) da[q] = 0.0f;
#pragma unroll 4
        for (int kt = 0; kt < 16; kt++) {
            unsigned bb0 = *(const unsigned*)&S->uT[nb * SKA + kt * 16 + c2];
            unsigned bb1 = *(const unsigned*)&S->uT[nb * SKA + kt * 16 + c2 + 8];
            uint4 f = ((const uint4*)inpf)[(kt * 64 + mtg) * 32 + lane];
            mma16816(da, f.x, f.y, f.z, f.w, bb0, bb1);
        }
        {
            int j = mtg * 16 + r;
            if (sA < 2) {        // xm: local + remote
#pragma unroll
                for (int q = 0; q < 4; q++) {
                    int jj = j + (q >> 1) * 8, n = c2 + (q & 1);
                    float pre = da[q] * S->cw1[jj] + S->cb[jj];
                    __half v = __float2half(pre * sigf(pre));
                    S->xmT[n * SKB + jj] = v;
                    stc_u16(sh32(&S->xmT[n * SKB + jj]) + dpeer, v);
                }
            } else {             // zs: local only (D split matches)
                int jz = j - 512;
#pragma unroll
                for (int q = 0; q < 4; q++) {
                    int jj = jz + (q >> 1) * 8, n = c2 + (q & 1);
                    float z = da[q];
                    S->zsT[n * SKB + jj] = __float2half(z * sigf(z));
                }
            }
        }
        CLUSTER_SYNC();

        // ---- C: x_dbl = xm @ x_proj^T (duplicated in both ranks, warps 0-3) ----
        if (w < 4) {
            float dc[4] = {0, 0, 0, 0};
#pragma unroll 4
            for (int kt = 0; kt < 32; kt++) {
                unsigned bb0 = *(const unsigned*)&S->xmT[nb * SKB + kt * 16 + c2];
                unsigned bb1 = *(const unsigned*)&S->xmT[nb * SKB + kt * 16 + c2 + 8];
                uint4 f = ((const uint4*)xpf)[(kt * 4 + w) * 32 + lane];
                mma16816(dc, f.x, f.y, f.z, f.w, bb0, bb1);
            }
            int o = w * 16 + r;
            S->xdbl[(c2    ) * 64 + o    ] = dc[0];
            S->xdbl[(c2 + 1) * 64 + o    ] = dc[1];
            S->xdbl[(c2    ) * 64 + o + 8] = dc[2];
            S->xdbl[(c2 + 1) * 64 + o + 8] = dc[3];
        }
        __syncthreads();

        // ---- D: (split by j-half) bcs inline, delta/softplus, y ----
        {
            int jl = tid & 255;
            int j  = (jl & 127) + ((jl >> 7) << 8) + p * 128;   // rank's 256 j's
            int nh = tid >> 8;                                   // 0..3 -> 2 n each
            float wr[16];
#pragma unroll
            for (int q = 0; q < 16; q++) wr[q] = __half2float(S->dtw[j * 16 + q]);
            float dtbj = S->dtb[j], dmj = S->dm[j];
#pragma unroll
            for (int nn = 0; nn < 2; nn++) {
                int n = nh * 2 + nn;
                float bcs = 0.0f;
#pragma unroll
                for (int ss = 0; ss < 16; ss++)
                    bcs += S->xdbl[n * 64 + 16 + ss] * S->xdbl[n * 64 + 32 + ss];
                float s = dtbj;
#pragma unroll
                for (int rr = 0; rr < 16; rr++) s += S->xdbl[n * 64 + rr] * wr[rr];
                float delta = fmaxf(s, 0.0f) + __logf(1.0f + __expf(-fabsf(s)));
                float y = (delta * bcs + dmj) * __half2float(S->xmT[n * SKB + j])
                                              * __half2float(S->zsT[n * SKB + j]);
                __half v = __float2half(y);
                S->yT[n * SKB + j] = v;
                stc_u16(sh32(&S->yT[n * SKB + j]) + dpeer, v);
            }
        }
        CLUSTER_SYNC();

        // ---- E: mamba_out partials (warps 0-15: 8 tiles x 2-way K-split) ----
        if (w < 16) {
            int tile = w & 7, kh = w >> 3;
            int mt = p * 8 + tile;
            float de[4] = {0, 0, 0, 0};
#pragma unroll 4
            for (int kk = 0; kk < 16; kk++) {
                int kt = kh * 16 + kk;
                unsigned bb0 = *(const unsigned*)&S->yT[nb * SKB + kt * 16 + c2];
                unsigned bb1 = *(const unsigned*)&S->yT[nb * SKB + kt * 16 + c2 + 8];
                uint4 f = ((const uint4*)outpf)[(kt * 16 + mt) * 32 + lane];
                mma16816(de, f.x, f.y, f.z, f.w, bb0, bb1);
            }
#pragma unroll
            for (int q = 0; q < 4; q++) S->epart[kh][tile][lane][q] = de[q];
        }
        __syncthreads();

        // ---- F: gates, state, output (warps 0-7: rank's j-half) ----
        if (w < 8) {
            int tile = w;
            int mt = p * 8 + tile;
            int t_out = dd ? (TLEN - 1 - t) : t;
#pragma unroll
            for (int q = 0; q < 4; q++) {
                int jj = mt * 16 + r + (q >> 1) * 8;    // in [128p, 128p+128)
                int n  = c2 + (q & 1);
                int ix = n * 256 + jj;
                float ipre = S->epart[0][tile][lane][q] + S->epart[1][tile][lane][q];
                float iv = sigf(ipre + S->bsum[jj]);
                float fv = sigf(S->gates[0][ix] + S->bsum[256 + jj]);
                float gv = tanha(S->gates[1][ix] + S->bsum[512 + jj]);
                float ov = sigf(S->gates[2][ix] + S->bsum[768 + jj]);
                float cn = fv * S->cst[ix] + iv * gv;
                float hn = ov * tanha(cn);
                S->cst[ix] = cn;
                __half hv = __float2half(hn);
                S->hT[n * SKA + jj] = hv;
                stc_u16(sh32(&S->hT[n * SKA + jj]) + dpeer, hv);
                outbuf[((size_t)(b0g + n) * TLEN + t_out) * 512 + dd * 256 + jj] = hn;
            }
        }
        CLUSTER_SYNC();
    }

    // final states: rank stores its j-half
    {
        int n = tid >> 7, jl = tid & 127;
        int j = p * 128 + jl;
        g_h[((size_t)dd * BSZ + b0g + n) * H + j] = __half2float(S->hT[n * SKA + j]);
        g_c[((size_t)dd * BSZ + b0g + n) * H + j] = S->cst[n * 256 + j];
    }
    CLUSTER_SYNC();
}

// =====================================================================
extern "C" void kernel_launch(void* const* d_in, const int* in_sizes, int n_in,
                              void* d_out, int out_size)
{
    (void)in_sizes; (void)n_in; (void)out_size;
    const float* x        = (const float*)d_in[0];
    const float* w_ih_l0  = (const float*)d_in[1];
    const float* w_hh_l0  = (const float*)d_in[2];
    const float* b_ih_l0  = (const float*)d_in[3];
    const float* b_hh_l0  = (const float*)d_in[4];
    const float* w_ih_l1  = (const float*)d_in[5];
    const float* w_hh_l1  = (const float*)d_in[6];
    const float* b_ih_l1  = (const float*)d_in[7];
    const float* b_hh_l1  = (const float*)d_in[8];
    const float* in_proj  = (const float*)d_in[9];
    const float* conv_w   = (const float*)d_in[10];
    const float* conv_b   = (const float*)d_in[11];
    const float* x_proj   = (const float*)d_in[12];
    const float* dt_w     = (const float*)d_in[13];
    const float* dt_b     = (const float*)d_in[14];
    const float* Dm       = (const float*)d_in[15];
    const float* out_proj = (const float*)d_in[16];
    float* out = (float*)d_out;

    static int inited = 0;
    int smem_bytes = (int)sizeof(SS);
    if (!inited) {
        cudaFuncSetAttribute(scan_kernel, cudaFuncAttributeMaxDynamicSharedMemorySize, smem_bytes);
        inited = 1;
    }

    float*  out0;   cudaGetSymbolAddress((void**)&out0,   g_out0);
    __half* whhf;   cudaGetSymbolAddress((void**)&whhf,   g_whhf);
    __half* inpf;   cudaGetSymbolAddress((void**)&inpf,   g_inpf);
    __half* outpf;  cudaGetSymbolAddress((void**)&outpf,  g_outpf);
    __half* xpf;    cudaGetSymbolAddress((void**)&xpf,    g_xpf);
    __half* wihf0;  cudaGetSymbolAddress((void**)&wihf0,  g_wihf0);
    __half* wihf1;  cudaGetSymbolAddress((void**)&wihf1,  g_wihf1);
    __half* xbf;    cudaGetSymbolAddress((void**)&xbf,    g_xbf);

    // layer-independent frag weights
    prepfrag<<<(16 * 64 * 256 + 255) / 256, 256>>>(in_proj, inpf, 64, 16, 1024);
    prepfrag<<<(32 * 16 * 256 + 255) / 256, 256>>>(out_proj, outpf, 16, 32, 256);
    prepfrag<<<(32 * 4 * 256 + 255) / 256, 256>>>(x_proj, xpf, 4, 32, 48);
    prepfrag<<<(8 * 64 * 256 + 255) / 256, 256>>>(w_ih_l0, wihf0, 64, 8, 1024);
    prepfrag<<<(8 * 64 * 256 + 255) / 256, 256>>>(w_ih_l0 + (size_t)G4 * 128,
                                                  wihf0 + 8 * 64 * 256, 64, 8, 1024);
    prepfrag<<<(32 * 64 * 256 + 255) / 256, 256>>>(w_ih_l1, wihf1, 64, 32, 1024);
    prepfrag<<<(32 * 64 * 256 + 255) / 256, 256>>>(w_ih_l1 + (size_t)G4 * 512,
                                                   wihf1 + 32 * 64 * 256, 64, 32, 1024);

    // ---- layer 0 ----
    prepfrag<<<(16 * 64 * 256 + 255) / 256, 256>>>(w_hh_l0, whhf, 64, 16, 1024);
    prepfrag<<<(16 * 64 * 256 + 255) / 256, 256>>>(w_hh_l0 + (size_t)G4 * H,
                                                   whhf + 16 * 64 * 256, 64, 16, 1024);
    conv_bfrag<<<(TLEN * 8 * 2048 + 255) / 256, 256>>>(x, xbf, 8, 128);
    wx_hmma<<<dim3(TLEN, 8, 2), 512>>>(xbf, wihf0, 8);
    scan_kernel<<<128, 1024, smem_bytes>>>(whhf, b_ih_l0, b_hh_l0, inpf, outpf, xpf,
        conv_w, conv_b, dt_w, dt_b, Dm, out0, 1);

    // ---- layer 1 ----
    prepfrag<<<(16 * 64 * 256 + 255) / 256, 256>>>(w_hh_l1, whhf, 64, 16, 1024);
    prepfrag<<<(16 * 64 * 256 + 255) / 256, 256>>>(w_hh_l1 + (size_t)G4 * H,
                                                   whhf + 16 * 64 * 256, 64, 16, 1024);
    conv_bfrag<<<(TLEN * 32 * 2048 + 255) / 256, 256>>>(out0, xbf, 32, 512);
    wx_hmma<<<dim3(TLEN, 8, 2), 512>>>(xbf, wihf1, 32);
    scan_kernel<<<128, 1024, smem_bytes>>>(whhf, b_ih_l1, b_hh_l1, inpf, outpf, xpf,
        conv_w, conv_b, dt_w, dt_b, Dm, out, 0);
}